// round 15
// baseline (speedup 1.0000x reference)
#include <cuda_runtime.h>
#include <cuda_fp16.h>
#include <cstdint>
#include <math.h>

#define NSTEP 8192
#define NMOD  4096
#define DIM   1024
#define INVT  (1.0f / 0.07f)

#define KC 32
#define NCHUNK (DIM / KC)
#define NSLOT 6
#define STAGE_H 16384                  // 1 chunk: A 8192 + B 8192 halves
#define STAGE_BYTES (STAGE_H * 2)      // 32KB
#define SMEM_BYTES (NSLOT * STAGE_BYTES)   // 192KB

// ---------------- device scratch (static, allowed) ----------------
__device__ __align__(16) __half g_As[(size_t)64 * NCHUNK * 8192];
__device__ __align__(16) __half g_Bs[(size_t)32 * NCHUNK * 8192];
__device__ __align__(16) __half g_Cs[(size_t)32 * NCHUNK * 8192];

__device__ float    g_inva[NSTEP];
__device__ float    g_invb[NMOD];
__device__ float    g_invc[NMOD];
__device__ unsigned g_negmax[NSTEP];
__device__ unsigned g_posmaxR[NSTEP];
__device__ unsigned g_posmaxS[NSTEP];
__device__ float    g_perstep[NSTEP];
__device__ float    g_wsum[NSTEP];
__device__ unsigned g_done;

__device__ __forceinline__ unsigned fenc(float f) {
    unsigned u = __float_as_uint(f);
    return (u & 0x80000000u) ? ~u : (u | 0x80000000u);
}
__device__ __forceinline__ float fdec(unsigned u) {
    return (u & 0x80000000u) ? __uint_as_float(u & 0x7FFFFFFFu)
                             : __uint_as_float(~u);
}
__device__ __forceinline__ uint32_t smem_u32(const void* p) {
    uint32_t a;
    asm("{ .reg .u64 t; cvta.to.shared.u64 t, %1; cvt.u32.u64 %0, t; }"
        : "=r"(a) : "l"(p));
    return a;
}
__device__ __forceinline__ void mbar_init(uint32_t a, uint32_t c) {
    asm volatile("mbarrier.init.shared.b64 [%0], %1;" :: "r"(a), "r"(c) : "memory");
}
__device__ __forceinline__ void mbar_expect_tx(uint32_t a, uint32_t bytes) {
    asm volatile("mbarrier.arrive.expect_tx.shared.b64 _, [%0], %1;"
                 :: "r"(a), "r"(bytes) : "memory");
}
__device__ __forceinline__ void mbar_arrive(uint32_t a) {
    asm volatile("mbarrier.arrive.shared.b64 _, [%0];" :: "r"(a) : "memory");
}
__device__ __forceinline__ void mbar_wait(uint32_t a, uint32_t par) {
    asm volatile(
        "{\n\t.reg .pred P;\n\t"
        "WL%=:\n\t"
        "mbarrier.try_wait.parity.acquire.cta.shared::cta.b64 P, [%0], %1, 0x989680;\n\t"
        "@P bra.uni WD%=;\n\t"
        "bra.uni WL%=;\n\t"
        "WD%=:\n\t}"
        :: "r"(a), "r"(par) : "memory");
}
__device__ __forceinline__ void bulk_cp(uint32_t dst, const void* src,
                                        uint32_t bytes, uint32_t mbar) {
    asm volatile(
        "cp.async.bulk.shared::cta.global.mbarrier::complete_tx::bytes [%0], [%1], %2, [%3];"
        :: "r"(dst), "l"(src), "r"(bytes), "r"(mbar) : "memory");
}
__device__ __forceinline__ void splt(float2 v, uint32_t& h, uint32_t& l) {
    __half2 hh = __floats2half2_rn(v.x, v.y);
    float2 hf = __half22float2(hh);
    __half2 ll = __floats2half2_rn(v.x - hf.x, v.y - hf.y);
    h = *reinterpret_cast<uint32_t*>(&hh);
    l = *reinterpret_cast<uint32_t*>(&ll);
}
__device__ __forceinline__ void mma16(float* c, uint4 a, uint32_t b0, uint32_t b1) {
    asm volatile(
        "mma.sync.aligned.m16n8k16.row.col.f32.f16.f16.f32 "
        "{%0,%1,%2,%3}, {%4,%5,%6,%7}, {%8,%9}, {%0,%1,%2,%3};"
        : "+f"(c[0]), "+f"(c[1]), "+f"(c[2]), "+f"(c[3])
        : "r"(a.x), "r"(a.y), "r"(a.z), "r"(a.w), "r"(b0), "r"(b1));
}

// ---------------- merged prep: split (blocks 0..4095) + norms (4096..6143) --
__global__ void prep_kernel(const float* __restrict__ A,
                            const float* __restrict__ B,
                            const float* __restrict__ C) {
    const int blk = blockIdx.x;
    const int tid = threadIdx.x;
    if (blk < 4096) {
        const int ch = blk >> 7, by = blk & 127;
        if (by < 64) {
            const int rb = by;
            __half* base = g_As + ((size_t)rb * NCHUNK + ch) * 8192;
#pragma unroll
            for (int i = 0; i < 2; i++) {
                int s = tid + i * 256;       // [m16(8)][k16(2)][lane(32)]
                int m16 = s >> 6, ki = (s >> 5) & 1, lane = s & 31;
                int g = lane >> 2, t = lane & 3;
                int r0 = rb * 128 + m16 * 16 + g;
                int c0 = ch * KC + ki * 16 + 2 * t;
                float2 v00 = *reinterpret_cast<const float2*>(A + (size_t)r0 * DIM + c0);
                float2 v10 = *reinterpret_cast<const float2*>(A + (size_t)(r0 + 8) * DIM + c0);
                float2 v01 = *reinterpret_cast<const float2*>(A + (size_t)r0 * DIM + c0 + 8);
                float2 v11 = *reinterpret_cast<const float2*>(A + (size_t)(r0 + 8) * DIM + c0 + 8);
                uint4 hi, lo;
                splt(v00, hi.x, lo.x);
                splt(v10, hi.y, lo.y);
                splt(v01, hi.z, lo.z);
                splt(v11, hi.w, lo.w);
                int off16 = (m16 * 2 + ki) * 32 + lane;
                *reinterpret_cast<uint4*>(base + off16 * 8)        = hi;
                *reinterpret_cast<uint4*>(base + 4096 + off16 * 8) = lo;
            }
        } else {
            const bool isB = by < 96;
            const int cb = isB ? (by - 64) : (by - 96);
            const float* src = isB ? B : C;
            __half* base = (isB ? g_Bs : g_Cs) + ((size_t)cb * NCHUNK + ch) * 8192;
#pragma unroll
            for (int i = 0; i < 2; i++) {
                int s = tid + i * 256;       // [n8(16)][lane(32)]
                int n8 = s >> 5, lane = s & 31;
                int g = lane >> 2, t = lane & 3;
                int row = cb * 128 + n8 * 8 + g;
                const float* rp = src + (size_t)row * DIM + ch * KC;
                float2 v0 = *reinterpret_cast<const float2*>(rp + 2 * t);
                float2 v1 = *reinterpret_cast<const float2*>(rp + 2 * t + 8);
                float2 v2 = *reinterpret_cast<const float2*>(rp + 16 + 2 * t);
                float2 v3 = *reinterpret_cast<const float2*>(rp + 16 + 2 * t + 8);
                uint4 hi, lo;
                splt(v0, hi.x, lo.x);
                splt(v1, hi.y, lo.y);
                splt(v2, hi.z, lo.z);
                splt(v3, hi.w, lo.w);
                int off16 = n8 * 32 + lane;
                *reinterpret_cast<uint4*>(base + off16 * 8)        = hi;
                *reinterpret_cast<uint4*>(base + 4096 + off16 * 8) = lo;
            }
        }
    } else {
        const int gw   = (blk - 4096) * 8 + (tid >> 5);
        const int lane = tid & 31;
        if (blk == 4096 && tid == 0) g_done = 0;
        const float* src;
        float* dst;
        int row;
        if (gw < NSTEP)              { src = A; dst = g_inva; row = gw; }
        else if (gw < NSTEP + NMOD)  { src = B; dst = g_invb; row = gw - NSTEP; }
        else                         { src = C; dst = g_invc; row = gw - NSTEP - NMOD; }
        const float4* p = reinterpret_cast<const float4*>(src + (size_t)row * DIM);
        float s = 0.0f;
#pragma unroll
        for (int i = 0; i < 8; i++) {
            float4 v = p[lane + 32 * i];
            s += v.x * v.x + v.y * v.y + v.z * v.z + v.w * v.w;
        }
#pragma unroll
        for (int o = 16; o > 0; o >>= 1)
            s += __shfl_xor_sync(0xFFFFFFFF, s, o);
        if (lane == 0) {
            dst[row] = 1.0f / fmaxf(sqrtf(s), 1e-8f);
            if (gw < NSTEP) {
                g_negmax[row]  = 0u;
                g_posmaxR[row] = 0u;
                g_posmaxS[row] = 0u;
            }
        }
    }
}

// ---------------- fp16 3-pass GEMM: 6-slot bulk-copy mbarrier ring ---------
__global__ __launch_bounds__(512, 1)
void gemm_mma(const __half* __restrict__ As, const __half* __restrict__ Bs,
              const __half* __restrict__ Cs, float* __restrict__ Rout) {
    extern __shared__ __half smem[];
    __shared__ __align__(8) unsigned long long mbar[2 * NSLOT];
    const int tid = threadIdx.x, lane = tid & 31, wid = tid >> 5;
    const int g = lane >> 2, t = lane & 3;
    const int wr = wid >> 2, wc = wid & 3;
    const bool store = blockIdx.x < 32;
    const int cb = blockIdx.x & 31;
    const int rowBase = blockIdx.y * 128, colBase = cb * 128;
    const uint32_t sb0 = smem_u32(smem);
    const uint32_t mb  = smem_u32(mbar);
    const __half* Ablk = As + (size_t)blockIdx.y * NCHUNK * 8192;
    const __half* Bblk = (store ? Bs : Cs) + (size_t)cb * NCHUNK * 8192;

    if (tid == 0) {
#pragma unroll
        for (int s = 0; s < NSLOT; s++) {
            mbar_init(mb + s * 8, 1);                 // full: expect_tx
            mbar_init(mb + NSLOT * 8 + s * 8, 16);    // empty: 1/warp
        }
    }
    __syncthreads();

    float acc[2][4][4];
#pragma unroll
    for (int i = 0; i < 2; i++)
#pragma unroll
        for (int j = 0; j < 4; j++)
#pragma unroll
            for (int q = 0; q < 4; q++) acc[i][j][q] = 0.0f;

    auto issue = [&](int st) {
        int slot = st % NSLOT;
        uint32_t fullb  = mb + slot * 8;
        uint32_t emptyb = mb + NSLOT * 8 + slot * 8;
        mbar_wait(emptyb, 1u ^ ((uint32_t)(st / NSLOT) & 1u));
        mbar_expect_tx(fullb, STAGE_BYTES);
        bulk_cp(sb0 + slot * STAGE_BYTES, Ablk + (size_t)st * 8192, 16384, fullb);
        bulk_cp(sb0 + slot * STAGE_BYTES + 16384, Bblk + (size_t)st * 8192, 16384, fullb);
    };

    if (tid == 0) {
#pragma unroll
        for (int s = 0; s < NSLOT - 1; s++) issue(s);
    }

    for (int ch = 0; ch < NCHUNK; ch++) {
        const int slot = ch % NSLOT;
        mbar_wait(mb + slot * 8, (uint32_t)(ch / NSLOT) & 1u);

        const __half* S  = smem + slot * STAGE_H;
        const __half* SB = S + 8192;
#pragma unroll
        for (int ki = 0; ki < 2; ki++) {
            uint4 ah[2], al[2];
#pragma unroll
            for (int mt = 0; mt < 2; mt++) {
                const __half* ap = S + (((wr * 2 + mt) * 2 + ki) * 32 + lane) * 8;
                ah[mt] = *reinterpret_cast<const uint4*>(ap);
                al[mt] = *reinterpret_cast<const uint4*>(ap + 4096);
            }
            uint2 bh[4], bl[4];
#pragma unroll
            for (int nt = 0; nt < 4; nt++) {
                const __half* bp = SB + ((wc * 4 + nt) * 32 + lane) * 8 + ki * 4;
                bh[nt] = *reinterpret_cast<const uint2*>(bp);
                bl[nt] = *reinterpret_cast<const uint2*>(bp + 4096);
            }
#pragma unroll
            for (int mt = 0; mt < 2; mt++)
#pragma unroll
                for (int nt = 0; nt < 4; nt++)
                    mma16(acc[mt][nt], ah[mt], bh[nt].x, bh[nt].y);
#pragma unroll
            for (int mt = 0; mt < 2; mt++)
#pragma unroll
                for (int nt = 0; nt < 4; nt++)
                    mma16(acc[mt][nt], ah[mt], bl[nt].x, bl[nt].y);
#pragma unroll
            for (int mt = 0; mt < 2; mt++)
#pragma unroll
                for (int nt = 0; nt < 4; nt++)
                    mma16(acc[mt][nt], al[mt], bh[nt].x, bh[nt].y);
        }

        if (lane == 0) mbar_arrive(mb + NSLOT * 8 + slot * 8);
        if (tid == 0 && ch + NSLOT - 1 < NCHUNK) issue(ch + NSLOT - 1);
    }

    // ---------------- epilogue ----------------
    if (store) {
        float mR0[2], mR1[2], mS0[2], mS1[2];
#pragma unroll
        for (int mt = 0; mt < 2; mt++) {
            mR0[mt] = mR1[mt] = mS0[mt] = mS1[mt] = -3.402823466e38f;
        }
#pragma unroll
        for (int mt = 0; mt < 2; mt++) {
            int r = rowBase + wr * 32 + mt * 16 + g;
#pragma unroll
            for (int nt = 0; nt < 4; nt++) {
                int c = colBase + wc * 32 + nt * 8 + 2 * t;
                float ib0 = g_invb[c], ib1 = g_invb[c + 1];
                float a0 = acc[mt][nt][0], a1 = acc[mt][nt][1];
                float a2 = acc[mt][nt][2], a3 = acc[mt][nt][3];
                mR0[mt] = fmaxf(mR0[mt], fmaxf(a0, a1));
                mR1[mt] = fmaxf(mR1[mt], fmaxf(a2, a3));
                mS0[mt] = fmaxf(mS0[mt], fmaxf(a0 * ib0, a1 * ib1));
                mS1[mt] = fmaxf(mS1[mt], fmaxf(a2 * ib0, a3 * ib1));
                *reinterpret_cast<float2*>(Rout + (size_t)r * NMOD + c) =
                    make_float2(a0, a1);
                *reinterpret_cast<float2*>(Rout + (size_t)(r + 8) * NMOD + c) =
                    make_float2(a2, a3);
            }
        }
#pragma unroll
        for (int mt = 0; mt < 2; mt++) {
#pragma unroll
            for (int o = 1; o <= 2; o <<= 1) {
                mR0[mt] = fmaxf(mR0[mt], __shfl_xor_sync(0xFFFFFFFF, mR0[mt], o));
                mR1[mt] = fmaxf(mR1[mt], __shfl_xor_sync(0xFFFFFFFF, mR1[mt], o));
                mS0[mt] = fmaxf(mS0[mt], __shfl_xor_sync(0xFFFFFFFF, mS0[mt], o));
                mS1[mt] = fmaxf(mS1[mt], __shfl_xor_sync(0xFFFFFFFF, mS1[mt], o));
            }
        }
        if (t == 0) {
#pragma unroll
            for (int mt = 0; mt < 2; mt++) {
                int r = rowBase + wr * 32 + mt * 16 + g;
                atomicMax(&g_posmaxR[r], fenc(mR0[mt]));
                atomicMax(&g_posmaxR[r + 8], fenc(mR1[mt]));
                atomicMax(&g_posmaxS[r], fenc(mS0[mt]));
                atomicMax(&g_posmaxS[r + 8], fenc(mS1[mt]));
            }
        }
    } else {
        float mx0[2], mx1[2];
#pragma unroll
        for (int mt = 0; mt < 2; mt++) { mx0[mt] = -3.402823466e38f; mx1[mt] = -3.402823466e38f; }
#pragma unroll
        for (int nt = 0; nt < 4; nt++) {
            int c = colBase + wc * 32 + nt * 8 + 2 * t;
            float ic0 = g_invc[c], ic1 = g_invc[c + 1];
#pragma unroll
            for (int mt = 0; mt < 2; mt++) {
                mx0[mt] = fmaxf(mx0[mt], fmaxf(acc[mt][nt][0] * ic0, acc[mt][nt][1] * ic1));
                mx1[mt] = fmaxf(mx1[mt], fmaxf(acc[mt][nt][2] * ic0, acc[mt][nt][3] * ic1));
            }
        }
#pragma unroll
        for (int mt = 0; mt < 2; mt++) {
            mx0[mt] = fmaxf(mx0[mt], __shfl_xor_sync(0xFFFFFFFF, mx0[mt], 1));
            mx0[mt] = fmaxf(mx0[mt], __shfl_xor_sync(0xFFFFFFFF, mx0[mt], 2));
            mx1[mt] = fmaxf(mx1[mt], __shfl_xor_sync(0xFFFFFFFF, mx1[mt], 1));
            mx1[mt] = fmaxf(mx1[mt], __shfl_xor_sync(0xFFFFFFFF, mx1[mt], 2));
        }
        if (t == 0) {
#pragma unroll
            for (int mt = 0; mt < 2; mt++) {
                int r = rowBase + wr * 32 + mt * 16 + g;
                atomicMax(&g_negmax[r], fenc(mx0[mt]));
                atomicMax(&g_negmax[r + 8], fenc(mx1[mt]));
            }
        }
    }
}

// ---------------- row softmax + fused last-block finalize ------------------
__global__ __launch_bounds__(512)
void row_stats_kernel(float* __restrict__ attn, float* __restrict__ perstep_out,
                      float* __restrict__ out) {
    __shared__ float sm[32];
    __shared__ float bc[2];
    __shared__ bool isLast;
    const int row = blockIdx.x;
    const int tid = threadIdx.x;
    const int lane = tid & 31, wid = tid >> 5;
    float* Rrow = attn + (size_t)row * NMOD;
    const float maxR = fdec(g_posmaxR[row]);

    float e[8];
    float dsum = 0.0f, ws = 0.0f;
#pragma unroll
    for (int q = 0; q < 8; q++) {
        int j = tid + q * 512;
        float v  = Rrow[j];
        float ev = __expf((v - maxR) * INVT);
        e[q] = ev;
        dsum += ev;
        ws   += v * g_invb[j] * ev;
    }
#pragma unroll
    for (int o = 16; o > 0; o >>= 1) {
        dsum += __shfl_xor_sync(0xFFFFFFFF, dsum, o);
        ws   += __shfl_xor_sync(0xFFFFFFFF, ws,   o);
    }
    if (lane == 0) { sm[wid] = dsum; sm[16 + wid] = ws; }
    __syncthreads();
    if (tid == 0) {
        float a = sm[0], b = sm[16];
#pragma unroll
        for (int w = 1; w < 16; w++) {
            a += sm[w];
            b += sm[16 + w];
        }
        bc[0] = a; bc[1] = b;
    }
    __syncthreads();

    const float invd = 1.0f / bc[0];
#pragma unroll
    for (int q = 0; q < 8; q++)
        Rrow[tid + q * 512] = e[q] * invd;

    if (tid == 0) {
        float inva = g_inva[row];
        float ps = fdec(g_posmaxS[row]) * inva;
        g_perstep[row]  = ps;
        perstep_out[row] = ps;
        g_wsum[row] = inva * bc[1] * invd;
    }

    // ---- last block runs the final scalar reduction ----
    __threadfence();
    if (tid == 0) isLast = (atomicAdd(&g_done, 1u) == NSTEP - 1);
    __syncthreads();
    if (!isLast) return;

    __shared__ float r0[512], r1[512], r2[512], r3[512];
    float s = 0.0f, mn = 3.402823466e38f, wsum = 0.0f, ng = 0.0f;
#pragma unroll
    for (int q = 0; q < 16; q++) {
        int i = tid + q * 512;
        float ps = g_perstep[i];
        s += ps;
        mn = fminf(mn, ps);
        wsum += g_wsum[i];
        ng += fdec(g_negmax[i]) * g_inva[i];
    }
    r0[tid] = s; r1[tid] = mn; r2[tid] = wsum; r3[tid] = ng;
    __syncthreads();
    for (int off = 256; off > 0; off >>= 1) {
        if (tid < off) {
            r0[tid] += r0[tid + off];
            r1[tid] = fminf(r1[tid], r1[tid + off]);
            r2[tid] += r2[tid + off];
            r3[tid] += r3[tid + off];
        }
        __syncthreads();
    }
    if (tid == 0) {
        float alignment = r0[0] * (1.0f / NSTEP);
        float weighted  = r2[0] * (1.0f / NSTEP);
        float neg       = r3[0] * (1.0f / NSTEP);
        float contrast  = alignment - neg;
        float margin    = fmaxf(contrast - 0.2f, 0.0f);
        float overall   = 0.7f * weighted + 0.3f * contrast;
        out[0] = alignment;
        out[1] = weighted;
        float* tl = out + 2 + (size_t)NSTEP * NMOD;
        tl[0] = contrast;
        tl[1] = margin;
        tl[2] = alignment;
        tl[3] = neg;
        tl[4 + NSTEP] = r1[0];
        tl[5 + NSTEP] = overall;
    }
}

// ---------------- launch ----------------
extern "C" void kernel_launch(void* const* d_in, const int* in_sizes, int n_in,
                              void* d_out, int out_size) {
    (void)in_sizes; (void)n_in; (void)out_size;
    const float* A = (const float*)d_in[0];
    const float* B = (const float*)d_in[1];
    const float* C = (const float*)d_in[2];
    float* out  = (float*)d_out;
    float* attn = out + 2;
    float* perstep = out + 2 + (size_t)NSTEP * NMOD + 4;

    __half* As_p; cudaGetSymbolAddress((void**)&As_p, g_As);
    __half* Bs_p; cudaGetSymbolAddress((void**)&Bs_p, g_Bs);
    __half* Cs_p; cudaGetSymbolAddress((void**)&Cs_p, g_Cs);

    cudaFuncSetAttribute(gemm_mma, cudaFuncAttributeMaxDynamicSharedMemorySize, SMEM_BYTES);

    prep_kernel<<<6144, 256>>>(A, B, C);
    gemm_mma<<<dim3(64, 64), 512, SMEM_BYTES>>>(As_p, Bs_p, Cs_p, attn);
    row_stats_kernel<<<NSTEP, 512>>>(attn, perstep, out);
}

// round 16
// speedup vs baseline: 1.0220x; 1.0220x over previous
#include <cuda_runtime.h>
#include <cuda_fp16.h>
#include <cstdint>
#include <math.h>

#define NSTEP 8192
#define NMOD  4096
#define DIM   1024
#define INVT  (1.0f / 0.07f)

#define KC 32
#define NCHUNK (DIM / KC)
#define STAGE_H 32768                  // 2 chunks: A 16384 + B 16384 halves
#define STAGE_BYTES (STAGE_H * 2)      // 64KB
#define SMEM_BYTES (3 * STAGE_BYTES)   // 192KB

// ---------------- device scratch (static, allowed) ----------------
__device__ __align__(16) __half g_As[(size_t)64 * NCHUNK * 8192];
__device__ __align__(16) __half g_Bs[(size_t)32 * NCHUNK * 8192];
__device__ __align__(16) __half g_Cs[(size_t)32 * NCHUNK * 8192];

__device__ float    g_inva[NSTEP];
__device__ float    g_invb[NMOD];
__device__ float    g_invc[NMOD];
__device__ unsigned g_negmax[NSTEP];
__device__ unsigned g_posmaxR[NSTEP];
__device__ unsigned g_posmaxS[NSTEP];
__device__ float    g_perstep[NSTEP];
__device__ float    g_wsum[NSTEP];
__device__ unsigned g_done;

__device__ __forceinline__ unsigned fenc(float f) {
    unsigned u = __float_as_uint(f);
    return (u & 0x80000000u) ? ~u : (u | 0x80000000u);
}
__device__ __forceinline__ float fdec(unsigned u) {
    return (u & 0x80000000u) ? __uint_as_float(u & 0x7FFFFFFFu)
                             : __uint_as_float(~u);
}
__device__ __forceinline__ uint32_t smem_u32(const void* p) {
    uint32_t a;
    asm("{ .reg .u64 t; cvta.to.shared.u64 t, %1; cvt.u32.u64 %0, t; }"
        : "=r"(a) : "l"(p));
    return a;
}
__device__ __forceinline__ void mbar_init(uint32_t a, uint32_t c) {
    asm volatile("mbarrier.init.shared.b64 [%0], %1;" :: "r"(a), "r"(c) : "memory");
}
__device__ __forceinline__ void mbar_expect_tx(uint32_t a, uint32_t bytes) {
    asm volatile("mbarrier.arrive.expect_tx.shared.b64 _, [%0], %1;"
                 :: "r"(a), "r"(bytes) : "memory");
}
__device__ __forceinline__ void mbar_arrive(uint32_t a) {
    asm volatile("mbarrier.arrive.shared.b64 _, [%0];" :: "r"(a) : "memory");
}
__device__ __forceinline__ void mbar_wait(uint32_t a, uint32_t par) {
    asm volatile(
        "{\n\t.reg .pred P;\n\t"
        "WL%=:\n\t"
        "mbarrier.try_wait.parity.acquire.cta.shared::cta.b64 P, [%0], %1, 0x989680;\n\t"
        "@P bra.uni WD%=;\n\t"
        "bra.uni WL%=;\n\t"
        "WD%=:\n\t}"
        :: "r"(a), "r"(par) : "memory");
}
__device__ __forceinline__ void bulk_cp(uint32_t dst, const void* src,
                                        uint32_t bytes, uint32_t mbar) {
    asm volatile(
        "cp.async.bulk.shared::cta.global.mbarrier::complete_tx::bytes [%0], [%1], %2, [%3];"
        :: "r"(dst), "l"(src), "r"(bytes), "r"(mbar) : "memory");
}
__device__ __forceinline__ void splt(float2 v, uint32_t& h, uint32_t& l) {
    __half2 hh = __floats2half2_rn(v.x, v.y);
    float2 hf = __half22float2(hh);
    __half2 ll = __floats2half2_rn(v.x - hf.x, v.y - hf.y);
    h = *reinterpret_cast<uint32_t*>(&hh);
    l = *reinterpret_cast<uint32_t*>(&ll);
}
__device__ __forceinline__ void mma16(float* c, uint4 a, uint32_t b0, uint32_t b1) {
    asm volatile(
        "mma.sync.aligned.m16n8k16.row.col.f32.f16.f16.f32 "
        "{%0,%1,%2,%3}, {%4,%5,%6,%7}, {%8,%9}, {%0,%1,%2,%3};"
        : "+f"(c[0]), "+f"(c[1]), "+f"(c[2]), "+f"(c[3])
        : "r"(a.x), "r"(a.y), "r"(a.z), "r"(a.w), "r"(b0), "r"(b1));
}

// ---------------- merged prep: split (blocks 0..4095) + norms (4096..6143) --
__global__ void prep_kernel(const float* __restrict__ A,
                            const float* __restrict__ B,
                            const float* __restrict__ C) {
    const int blk = blockIdx.x;
    const int tid = threadIdx.x;
    if (blk < 4096) {
        const int ch = blk >> 7, by = blk & 127;
        if (by < 64) {
            const int rb = by;
            __half* base = g_As + ((size_t)rb * NCHUNK + ch) * 8192;
#pragma unroll
            for (int i = 0; i < 2; i++) {
                int s = tid + i * 256;       // [m16(8)][k16(2)][lane(32)]
                int m16 = s >> 6, ki = (s >> 5) & 1, lane = s & 31;
                int g = lane >> 2, t = lane & 3;
                int r0 = rb * 128 + m16 * 16 + g;
                int c0 = ch * KC + ki * 16 + 2 * t;
                float2 v00 = *reinterpret_cast<const float2*>(A + (size_t)r0 * DIM + c0);
                float2 v10 = *reinterpret_cast<const float2*>(A + (size_t)(r0 + 8) * DIM + c0);
                float2 v01 = *reinterpret_cast<const float2*>(A + (size_t)r0 * DIM + c0 + 8);
                float2 v11 = *reinterpret_cast<const float2*>(A + (size_t)(r0 + 8) * DIM + c0 + 8);
                uint4 hi, lo;
                splt(v00, hi.x, lo.x);
                splt(v10, hi.y, lo.y);
                splt(v01, hi.z, lo.z);
                splt(v11, hi.w, lo.w);
                int off16 = (m16 * 2 + ki) * 32 + lane;
                *reinterpret_cast<uint4*>(base + off16 * 8)        = hi;
                *reinterpret_cast<uint4*>(base + 4096 + off16 * 8) = lo;
            }
        } else {
            const bool isB = by < 96;
            const int cb = isB ? (by - 64) : (by - 96);
            const float* src = isB ? B : C;
            __half* base = (isB ? g_Bs : g_Cs) + ((size_t)cb * NCHUNK + ch) * 8192;
#pragma unroll
            for (int i = 0; i < 2; i++) {
                int s = tid + i * 256;       // [n8(16)][lane(32)]
                int n8 = s >> 5, lane = s & 31;
                int g = lane >> 2, t = lane & 3;
                int row = cb * 128 + n8 * 8 + g;
                const float* rp = src + (size_t)row * DIM + ch * KC;
                float2 v0 = *reinterpret_cast<const float2*>(rp + 2 * t);
                float2 v1 = *reinterpret_cast<const float2*>(rp + 2 * t + 8);
                float2 v2 = *reinterpret_cast<const float2*>(rp + 16 + 2 * t);
                float2 v3 = *reinterpret_cast<const float2*>(rp + 16 + 2 * t + 8);
                uint4 hi, lo;
                splt(v0, hi.x, lo.x);
                splt(v1, hi.y, lo.y);
                splt(v2, hi.z, lo.z);
                splt(v3, hi.w, lo.w);
                int off16 = n8 * 32 + lane;
                *reinterpret_cast<uint4*>(base + off16 * 8)        = hi;
                *reinterpret_cast<uint4*>(base + 4096 + off16 * 8) = lo;
            }
        }
    } else {
        const int gw   = (blk - 4096) * 8 + (tid >> 5);
        const int lane = tid & 31;
        if (blk == 4096 && tid == 0) g_done = 0;
        const float* src;
        float* dst;
        int row;
        if (gw < NSTEP)              { src = A; dst = g_inva; row = gw; }
        else if (gw < NSTEP + NMOD)  { src = B; dst = g_invb; row = gw - NSTEP; }
        else                         { src = C; dst = g_invc; row = gw - NSTEP - NMOD; }
        const float4* p = reinterpret_cast<const float4*>(src + (size_t)row * DIM);
        float s = 0.0f;
#pragma unroll
        for (int i = 0; i < 8; i++) {
            float4 v = p[lane + 32 * i];
            s += v.x * v.x + v.y * v.y + v.z * v.z + v.w * v.w;
        }
#pragma unroll
        for (int o = 16; o > 0; o >>= 1)
            s += __shfl_xor_sync(0xFFFFFFFF, s, o);
        if (lane == 0) {
            dst[row] = 1.0f / fmaxf(sqrtf(s), 1e-8f);
            if (gw < NSTEP) {
                g_negmax[row]  = 0u;
                g_posmaxR[row] = 0u;
                g_posmaxS[row] = 0u;
            }
        }
    }
}

// ---------------- fp16 3-pass GEMM: 3-slot bulk-copy mbarrier ring ---------
__global__ __launch_bounds__(512, 1)
void gemm_mma(const __half* __restrict__ As, const __half* __restrict__ Bs,
              const __half* __restrict__ Cs, float* __restrict__ Rout) {
    extern __shared__ __half smem[];
    __shared__ __align__(8) unsigned long long mbar[6];   // full[0..2], empty[0..2]
    const int tid = threadIdx.x, lane = tid & 31, wid = tid >> 5;
    const int g = lane >> 2, t = lane & 3;
    const int wr = wid >> 2, wc = wid & 3;
    const bool store = blockIdx.x < 32;
    const int cb = blockIdx.x & 31;
    const int rowBase = blockIdx.y * 128, colBase = cb * 128;
    const uint32_t sb0 = smem_u32(smem);
    const uint32_t mb  = smem_u32(mbar);
    const __half* Ablk = As + (size_t)blockIdx.y * NCHUNK * 8192;
    const __half* Bblk = (store ? Bs : Cs) + (size_t)cb * NCHUNK * 8192;

    if (tid == 0) {
#pragma unroll
        for (int s = 0; s < 3; s++) {
            mbar_init(mb + s * 8, 1);        // full: expect_tx arrival
            mbar_init(mb + 24 + s * 8, 16);  // empty: 1 arrival per warp
        }
    }
    __syncthreads();

    float acc[2][4][4];
#pragma unroll
    for (int i = 0; i < 2; i++)
#pragma unroll
        for (int j = 0; j < 4; j++)
#pragma unroll
            for (int q = 0; q < 4; q++) acc[i][j][q] = 0.0f;

    auto issue = [&](int st) {
        int slot = st % 3;
        uint32_t fullb  = mb + slot * 8;
        uint32_t emptyb = mb + 24 + slot * 8;
        mbar_wait(emptyb, 1u ^ ((uint32_t)(st / 3) & 1u));
        mbar_expect_tx(fullb, STAGE_BYTES);
        bulk_cp(sb0 + slot * STAGE_BYTES, Ablk + (size_t)st * 16384, 32768, fullb);
        bulk_cp(sb0 + slot * STAGE_BYTES + 32768, Bblk + (size_t)st * 16384, 32768, fullb);
    };

    if (tid == 0) { issue(0); issue(1); issue(2); }

    const int NPAIR = NCHUNK / 2;   // 16
    for (int pr = 0; pr < NPAIR; pr++) {
        const int slot = pr % 3;
        mbar_wait(mb + slot * 8, (uint32_t)(pr / 3) & 1u);   // full, acquire

        const __half* ST = smem + slot * STAGE_H;
#pragma unroll
        for (int sub = 0; sub < 2; sub++) {
            const __half* S  = ST + sub * 8192;
            const __half* SB = ST + 16384 + sub * 8192;
#pragma unroll
            for (int ki = 0; ki < 2; ki++) {
                uint4 ah[2], al[2];
#pragma unroll
                for (int mt = 0; mt < 2; mt++) {
                    const __half* ap = S + (((wr * 2 + mt) * 2 + ki) * 32 + lane) * 8;
                    ah[mt] = *reinterpret_cast<const uint4*>(ap);
                    al[mt] = *reinterpret_cast<const uint4*>(ap + 4096);
                }
                uint2 bh[4], bl[4];
#pragma unroll
                for (int nt = 0; nt < 4; nt++) {
                    const __half* bp = SB + ((wc * 4 + nt) * 32 + lane) * 8 + ki * 4;
                    bh[nt] = *reinterpret_cast<const uint2*>(bp);
                    bl[nt] = *reinterpret_cast<const uint2*>(bp + 4096);
                }
#pragma unroll
                for (int mt = 0; mt < 2; mt++)
#pragma unroll
                    for (int nt = 0; nt < 4; nt++)
                        mma16(acc[mt][nt], ah[mt], bh[nt].x, bh[nt].y);
#pragma unroll
                for (int mt = 0; mt < 2; mt++)
#pragma unroll
                    for (int nt = 0; nt < 4; nt++)
                        mma16(acc[mt][nt], ah[mt], bl[nt].x, bl[nt].y);
#pragma unroll
                for (int mt = 0; mt < 2; mt++)
#pragma unroll
                    for (int nt = 0; nt < 4; nt++)
                        mma16(acc[mt][nt], al[mt], bh[nt].x, bh[nt].y);
            }
        }

        if (lane == 0) mbar_arrive(mb + 24 + slot * 8);   // consumed
        if (tid == 0 && pr + 3 < NPAIR) issue(pr + 3);
    }

    // ---------------- epilogue ----------------
    if (store) {
        float mR0[2], mR1[2], mS0[2], mS1[2];
#pragma unroll
        for (int mt = 0; mt < 2; mt++) {
            mR0[mt] = mR1[mt] = mS0[mt] = mS1[mt] = -3.402823466e38f;
        }
#pragma unroll
        for (int mt = 0; mt < 2; mt++) {
            int r = rowBase + wr * 32 + mt * 16 + g;
#pragma unroll
            for (int nt = 0; nt < 4; nt++) {
                int c = colBase + wc * 32 + nt * 8 + 2 * t;
                float ib0 = g_invb[c], ib1 = g_invb[c + 1];
                float a0 = acc[mt][nt][0], a1 = acc[mt][nt][1];
                float a2 = acc[mt][nt][2], a3 = acc[mt][nt][3];
                mR0[mt] = fmaxf(mR0[mt], fmaxf(a0, a1));
                mR1[mt] = fmaxf(mR1[mt], fmaxf(a2, a3));
                mS0[mt] = fmaxf(mS0[mt], fmaxf(a0 * ib0, a1 * ib1));
                mS1[mt] = fmaxf(mS1[mt], fmaxf(a2 * ib0, a3 * ib1));
                *reinterpret_cast<float2*>(Rout + (size_t)r * NMOD + c) =
                    make_float2(a0, a1);
                *reinterpret_cast<float2*>(Rout + (size_t)(r + 8) * NMOD + c) =
                    make_float2(a2, a3);
            }
        }
#pragma unroll
        for (int mt = 0; mt < 2; mt++) {
#pragma unroll
            for (int o = 1; o <= 2; o <<= 1) {
                mR0[mt] = fmaxf(mR0[mt], __shfl_xor_sync(0xFFFFFFFF, mR0[mt], o));
                mR1[mt] = fmaxf(mR1[mt], __shfl_xor_sync(0xFFFFFFFF, mR1[mt], o));
                mS0[mt] = fmaxf(mS0[mt], __shfl_xor_sync(0xFFFFFFFF, mS0[mt], o));
                mS1[mt] = fmaxf(mS1[mt], __shfl_xor_sync(0xFFFFFFFF, mS1[mt], o));
            }
        }
        if (t == 0) {
#pragma unroll
            for (int mt = 0; mt < 2; mt++) {
                int r = rowBase + wr * 32 + mt * 16 + g;
                atomicMax(&g_posmaxR[r], fenc(mR0[mt]));
                atomicMax(&g_posmaxR[r + 8], fenc(mR1[mt]));
                atomicMax(&g_posmaxS[r], fenc(mS0[mt]));
                atomicMax(&g_posmaxS[r + 8], fenc(mS1[mt]));
            }
        }
    } else {
        float mx0[2], mx1[2];
#pragma unroll
        for (int mt = 0; mt < 2; mt++) { mx0[mt] = -3.402823466e38f; mx1[mt] = -3.402823466e38f; }
#pragma unroll
        for (int nt = 0; nt < 4; nt++) {
            int c = colBase + wc * 32 + nt * 8 + 2 * t;
            float ic0 = g_invc[c], ic1 = g_invc[c + 1];
#pragma unroll
            for (int mt = 0; mt < 2; mt++) {
                mx0[mt] = fmaxf(mx0[mt], fmaxf(acc[mt][nt][0] * ic0, acc[mt][nt][1] * ic1));
                mx1[mt] = fmaxf(mx1[mt], fmaxf(acc[mt][nt][2] * ic0, acc[mt][nt][3] * ic1));
            }
        }
#pragma unroll
        for (int mt = 0; mt < 2; mt++) {
            mx0[mt] = fmaxf(mx0[mt], __shfl_xor_sync(0xFFFFFFFF, mx0[mt], 1));
            mx0[mt] = fmaxf(mx0[mt], __shfl_xor_sync(0xFFFFFFFF, mx0[mt], 2));
            mx1[mt] = fmaxf(mx1[mt], __shfl_xor_sync(0xFFFFFFFF, mx1[mt], 1));
            mx1[mt] = fmaxf(mx1[mt], __shfl_xor_sync(0xFFFFFFFF, mx1[mt], 2));
        }
        if (t == 0) {
#pragma unroll
            for (int mt = 0; mt < 2; mt++) {
                int r = rowBase + wr * 32 + mt * 16 + g;
                atomicMax(&g_negmax[r], fenc(mx0[mt]));
                atomicMax(&g_negmax[r + 8], fenc(mx1[mt]));
            }
        }
    }
}

// ---------------- row softmax + fused last-block finalize ------------------
__global__ __launch_bounds__(512)
void row_stats_kernel(float* __restrict__ attn, float* __restrict__ perstep_out,
                      float* __restrict__ out) {
    __shared__ float sm[32];
    __shared__ float bc[2];
    __shared__ bool isLast;
    const int row = blockIdx.x;
    const int tid = threadIdx.x;
    const int lane = tid & 31, wid = tid >> 5;
    float* Rrow = attn + (size_t)row * NMOD;
    const float maxR = fdec(g_posmaxR[row]);

    float e[8];
    float dsum = 0.0f, ws = 0.0f;
#pragma unroll
    for (int q = 0; q < 8; q++) {
        int j = tid + q * 512;
        float v  = Rrow[j];
        float ev = __expf((v - maxR) * INVT);
        e[q] = ev;
        dsum += ev;
        ws   += v * g_invb[j] * ev;
    }
#pragma unroll
    for (int o = 16; o > 0; o >>= 1) {
        dsum += __shfl_xor_sync(0xFFFFFFFF, dsum, o);
        ws   += __shfl_xor_sync(0xFFFFFFFF, ws,   o);
    }
    if (lane == 0) { sm[wid] = dsum; sm[16 + wid] = ws; }
    __syncthreads();
    if (tid == 0) {
        float a = sm[0], b = sm[16];
#pragma unroll
        for (int w = 1; w < 16; w++) {
            a += sm[w];
            b += sm[16 + w];
        }
        bc[0] = a; bc[1] = b;
    }
    __syncthreads();

    const float invd = 1.0f / bc[0];
#pragma unroll
    for (int q = 0; q < 8; q++)
        Rrow[tid + q * 512] = e[q] * invd;

    if (tid == 0) {
        float inva = g_inva[row];
        float ps = fdec(g_posmaxS[row]) * inva;
        g_perstep[row]  = ps;
        perstep_out[row] = ps;
        g_wsum[row] = inva * bc[1] * invd;
    }

    // ---- last block runs the final scalar reduction ----
    __threadfence();
    if (tid == 0) isLast = (atomicAdd(&g_done, 1u) == NSTEP - 1);
    __syncthreads();
    if (!isLast) return;

    __shared__ float r0[512], r1[512], r2[512], r3[512];
    float s = 0.0f, mn = 3.402823466e38f, wsum = 0.0f, ng = 0.0f;
#pragma unroll
    for (int q = 0; q < 16; q++) {
        int i = tid + q * 512;
        float ps = g_perstep[i];
        s += ps;
        mn = fminf(mn, ps);
        wsum += g_wsum[i];
        ng += fdec(g_negmax[i]) * g_inva[i];
    }
    r0[tid] = s; r1[tid] = mn; r2[tid] = wsum; r3[tid] = ng;
    __syncthreads();
    for (int off = 256; off > 0; off >>= 1) {
        if (tid < off) {
            r0[tid] += r0[tid + off];
            r1[tid] = fminf(r1[tid], r1[tid + off]);
            r2[tid] += r2[tid + off];
            r3[tid] += r3[tid + off];
        }
        __syncthreads();
    }
    if (tid == 0) {
        float alignment = r0[0] * (1.0f / NSTEP);
        float weighted  = r2[0] * (1.0f / NSTEP);
        float neg       = r3[0] * (1.0f / NSTEP);
        float contrast  = alignment - neg;
        float margin    = fmaxf(contrast - 0.2f, 0.0f);
        float overall   = 0.7f * weighted + 0.3f * contrast;
        out[0] = alignment;
        out[1] = weighted;
        float* tl = out + 2 + (size_t)NSTEP * NMOD;
        tl[0] = contrast;
        tl[1] = margin;
        tl[2] = alignment;
        tl[3] = neg;
        tl[4 + NSTEP] = r1[0];
        tl[5 + NSTEP] = overall;
    }
}

// ---------------- launch ----------------
extern "C" void kernel_launch(void* const* d_in, const int* in_sizes, int n_in,
                              void* d_out, int out_size) {
    (void)in_sizes; (void)n_in; (void)out_size;
    const float* A = (const float*)d_in[0];
    const float* B = (const float*)d_in[1];
    const float* C = (const float*)d_in[2];
    float* out  = (float*)d_out;
    float* attn = out + 2;
    float* perstep = out + 2 + (size_t)NSTEP * NMOD + 4;

    __half* As_p; cudaGetSymbolAddress((void**)&As_p, g_As);
    __half* Bs_p; cudaGetSymbolAddress((void**)&Bs_p, g_Bs);
    __half* Cs_p; cudaGetSymbolAddress((void**)&Cs_p, g_Cs);

    cudaFuncSetAttribute(gemm_mma, cudaFuncAttributeMaxDynamicSharedMemorySize, SMEM_BYTES);

    prep_kernel<<<6144, 256>>>(A, B, C);
    gemm_mma<<<dim3(64, 64), 512, SMEM_BYTES>>>(As_p, Bs_p, Cs_p, attn);
    row_stats_kernel<<<NSTEP, 512>>>(attn, perstep, out);
}

// round 17
// speedup vs baseline: 1.0562x; 1.0335x over previous
#include <cuda_runtime.h>
#include <cuda_fp16.h>
#include <cstdint>
#include <math.h>

#define NSTEP 8192
#define NMOD  4096
#define DIM   1024
#define INVT  (1.0f / 0.07f)

#define KC 32
#define NCHUNK (DIM / KC)
#define STAGE_H 32768                  // 2 chunks: A 16384 + B 16384 halves
#define STAGE_BYTES (STAGE_H * 2)      // 64KB
#define SMEM_BYTES (3 * STAGE_BYTES)   // 192KB

// ---------------- device scratch (static, allowed) ----------------
__device__ __align__(16) __half g_As[(size_t)64 * NCHUNK * 8192];
__device__ __align__(16) __half g_Bs[(size_t)32 * NCHUNK * 8192];
__device__ __align__(16) __half g_Cs[(size_t)32 * NCHUNK * 8192];

__device__ float    g_inva[NSTEP];
__device__ float    g_invb[NMOD];
__device__ float    g_invc[NMOD];
__device__ unsigned g_negmax[NSTEP];
__device__ unsigned g_posmaxR[NSTEP];
__device__ unsigned g_posmaxS[NSTEP];
__device__ float    g_perstep[NSTEP];
__device__ float    g_wsum[NSTEP];

__device__ __forceinline__ unsigned fenc(float f) {
    unsigned u = __float_as_uint(f);
    return (u & 0x80000000u) ? ~u : (u | 0x80000000u);
}
__device__ __forceinline__ float fdec(unsigned u) {
    return (u & 0x80000000u) ? __uint_as_float(u & 0x7FFFFFFFu)
                             : __uint_as_float(~u);
}
__device__ __forceinline__ uint32_t smem_u32(const void* p) {
    uint32_t a;
    asm("{ .reg .u64 t; cvta.to.shared.u64 t, %1; cvt.u32.u64 %0, t; }"
        : "=r"(a) : "l"(p));
    return a;
}
__device__ __forceinline__ void mbar_init(uint32_t a, uint32_t c) {
    asm volatile("mbarrier.init.shared.b64 [%0], %1;" :: "r"(a), "r"(c) : "memory");
}
__device__ __forceinline__ void mbar_expect_tx(uint32_t a, uint32_t bytes) {
    asm volatile("mbarrier.arrive.expect_tx.shared.b64 _, [%0], %1;"
                 :: "r"(a), "r"(bytes) : "memory");
}
__device__ __forceinline__ void mbar_arrive(uint32_t a) {
    asm volatile("mbarrier.arrive.shared.b64 _, [%0];" :: "r"(a) : "memory");
}
__device__ __forceinline__ void mbar_wait(uint32_t a, uint32_t par) {
    asm volatile(
        "{\n\t.reg .pred P;\n\t"
        "WL%=:\n\t"
        "mbarrier.try_wait.parity.acquire.cta.shared::cta.b64 P, [%0], %1, 0x989680;\n\t"
        "@P bra.uni WD%=;\n\t"
        "bra.uni WL%=;\n\t"
        "WD%=:\n\t}"
        :: "r"(a), "r"(par) : "memory");
}
__device__ __forceinline__ void bulk_cp(uint32_t dst, const void* src,
                                        uint32_t bytes, uint32_t mbar) {
    asm volatile(
        "cp.async.bulk.shared::cta.global.mbarrier::complete_tx::bytes [%0], [%1], %2, [%3];"
        :: "r"(dst), "l"(src), "r"(bytes), "r"(mbar) : "memory");
}
__device__ __forceinline__ void splt(float2 v, uint32_t& h, uint32_t& l) {
    __half2 hh = __floats2half2_rn(v.x, v.y);
    float2 hf = __half22float2(hh);
    __half2 ll = __floats2half2_rn(v.x - hf.x, v.y - hf.y);
    h = *reinterpret_cast<uint32_t*>(&hh);
    l = *reinterpret_cast<uint32_t*>(&ll);
}
__device__ __forceinline__ void mma16(float* c, uint4 a, uint32_t b0, uint32_t b1) {
    asm volatile(
        "mma.sync.aligned.m16n8k16.row.col.f32.f16.f16.f32 "
        "{%0,%1,%2,%3}, {%4,%5,%6,%7}, {%8,%9}, {%0,%1,%2,%3};"
        : "+f"(c[0]), "+f"(c[1]), "+f"(c[2]), "+f"(c[3])
        : "r"(a.x), "r"(a.y), "r"(a.z), "r"(a.w), "r"(b0), "r"(b1));
}

// ---------------- merged prep: split (blocks 0..4095) + norms (4096..6143) --
__global__ void prep_kernel(const float* __restrict__ A,
                            const float* __restrict__ B,
                            const float* __restrict__ C) {
    const int blk = blockIdx.x;
    const int tid = threadIdx.x;
    if (blk < 4096) {
        const int ch = blk >> 7, by = blk & 127;
        if (by < 64) {
            const int rb = by;
            __half* base = g_As + ((size_t)rb * NCHUNK + ch) * 8192;
#pragma unroll
            for (int i = 0; i < 2; i++) {
                int s = tid + i * 256;       // [m16(8)][k16(2)][lane(32)]
                int m16 = s >> 6, ki = (s >> 5) & 1, lane = s & 31;
                int g = lane >> 2, t = lane & 3;
                int r0 = rb * 128 + m16 * 16 + g;
                int c0 = ch * KC + ki * 16 + 2 * t;
                float2 v00 = *reinterpret_cast<const float2*>(A + (size_t)r0 * DIM + c0);
                float2 v10 = *reinterpret_cast<const float2*>(A + (size_t)(r0 + 8) * DIM + c0);
                float2 v01 = *reinterpret_cast<const float2*>(A + (size_t)r0 * DIM + c0 + 8);
                float2 v11 = *reinterpret_cast<const float2*>(A + (size_t)(r0 + 8) * DIM + c0 + 8);
                uint4 hi, lo;
                splt(v00, hi.x, lo.x);
                splt(v10, hi.y, lo.y);
                splt(v01, hi.z, lo.z);
                splt(v11, hi.w, lo.w);
                int off16 = (m16 * 2 + ki) * 32 + lane;
                *reinterpret_cast<uint4*>(base + off16 * 8)        = hi;
                *reinterpret_cast<uint4*>(base + 4096 + off16 * 8) = lo;
            }
        } else {
            const bool isB = by < 96;
            const int cb = isB ? (by - 64) : (by - 96);
            const float* src = isB ? B : C;
            __half* base = (isB ? g_Bs : g_Cs) + ((size_t)cb * NCHUNK + ch) * 8192;
#pragma unroll
            for (int i = 0; i < 2; i++) {
                int s = tid + i * 256;       // [n8(16)][lane(32)]
                int n8 = s >> 5, lane = s & 31;
                int g = lane >> 2, t = lane & 3;
                int row = cb * 128 + n8 * 8 + g;
                const float* rp = src + (size_t)row * DIM + ch * KC;
                float2 v0 = *reinterpret_cast<const float2*>(rp + 2 * t);
                float2 v1 = *reinterpret_cast<const float2*>(rp + 2 * t + 8);
                float2 v2 = *reinterpret_cast<const float2*>(rp + 16 + 2 * t);
                float2 v3 = *reinterpret_cast<const float2*>(rp + 16 + 2 * t + 8);
                uint4 hi, lo;
                splt(v0, hi.x, lo.x);
                splt(v1, hi.y, lo.y);
                splt(v2, hi.z, lo.z);
                splt(v3, hi.w, lo.w);
                int off16 = n8 * 32 + lane;
                *reinterpret_cast<uint4*>(base + off16 * 8)        = hi;
                *reinterpret_cast<uint4*>(base + 4096 + off16 * 8) = lo;
            }
        }
    } else {
        const int gw   = (blk - 4096) * 8 + (tid >> 5);
        const int lane = tid & 31;
        const float* src;
        float* dst;
        int row;
        if (gw < NSTEP)              { src = A; dst = g_inva; row = gw; }
        else if (gw < NSTEP + NMOD)  { src = B; dst = g_invb; row = gw - NSTEP; }
        else                         { src = C; dst = g_invc; row = gw - NSTEP - NMOD; }
        const float4* p = reinterpret_cast<const float4*>(src + (size_t)row * DIM);
        float s = 0.0f;
#pragma unroll
        for (int i = 0; i < 8; i++) {
            float4 v = p[lane + 32 * i];
            s += v.x * v.x + v.y * v.y + v.z * v.z + v.w * v.w;
        }
#pragma unroll
        for (int o = 16; o > 0; o >>= 1)
            s += __shfl_xor_sync(0xFFFFFFFF, s, o);
        if (lane == 0) {
            dst[row] = 1.0f / fmaxf(sqrtf(s), 1e-8f);
            if (gw < NSTEP) {
                g_negmax[row]  = 0u;
                g_posmaxR[row] = 0u;
                g_posmaxS[row] = 0u;
            }
        }
    }
}

// ---------------- fp16 3-pass GEMM: 3-slot ring, distributed producer ------
__global__ __launch_bounds__(512, 1)
void gemm_mma(const __half* __restrict__ As, const __half* __restrict__ Bs,
              const __half* __restrict__ Cs, float* __restrict__ Rout) {
    extern __shared__ __half smem[];
    __shared__ __align__(8) unsigned long long mbar[6];   // full[0..2], empty[0..2]
    const int tid = threadIdx.x, lane = tid & 31, wid = tid >> 5;
    const int g = lane >> 2, t = lane & 3;
    const int wr = wid >> 2, wc = wid & 3;
    const bool store = blockIdx.x < 32;
    const int cb = blockIdx.x & 31;
    const int rowBase = blockIdx.y * 128, colBase = cb * 128;
    const uint32_t sb0 = smem_u32(smem);
    const uint32_t mb  = smem_u32(mbar);
    const __half* Ablk = As + (size_t)blockIdx.y * NCHUNK * 8192;
    const __half* Bblk = (store ? Bs : Cs) + (size_t)cb * NCHUNK * 8192;

    if (tid == 0) {
#pragma unroll
        for (int s = 0; s < 3; s++) {
            mbar_init(mb + s * 8, 1);        // full: expect_tx arrival
            mbar_init(mb + 24 + s * 8, 16);  // empty: 1 arrival per warp
        }
    }
    __syncthreads();

    float acc[2][4][4];
#pragma unroll
    for (int i = 0; i < 2; i++)
#pragma unroll
        for (int j = 0; j < 4; j++)
#pragma unroll
            for (int q = 0; q < 4; q++) acc[i][j][q] = 0.0f;

    // stage st (pair of chunks) is issued by lane 0 of warp (st & 15)
    auto issue = [&](int st) {
        int slot = st % 3;
        uint32_t fullb  = mb + slot * 8;
        uint32_t emptyb = mb + 24 + slot * 8;
        mbar_wait(emptyb, 1u ^ ((uint32_t)(st / 3) & 1u));
        mbar_expect_tx(fullb, STAGE_BYTES);
        bulk_cp(sb0 + slot * STAGE_BYTES, Ablk + (size_t)st * 16384, 32768, fullb);
        bulk_cp(sb0 + slot * STAGE_BYTES + 32768, Bblk + (size_t)st * 16384, 32768, fullb);
    };

    if (lane == 0 && wid < 3) issue(wid);   // prologue: stages 0..2 by warps 0..2

    const int NPAIR = NCHUNK / 2;   // 16
    for (int pr = 0; pr < NPAIR; pr++) {
        const int slot = pr % 3;
        mbar_wait(mb + slot * 8, (uint32_t)(pr / 3) & 1u);   // full, acquire

        const __half* ST = smem + slot * STAGE_H;
#pragma unroll
        for (int sub = 0; sub < 2; sub++) {
            const __half* S  = ST + sub * 8192;
            const __half* SB = ST + 16384 + sub * 8192;
#pragma unroll
            for (int ki = 0; ki < 2; ki++) {
                uint4 ah[2], al[2];
#pragma unroll
                for (int mt = 0; mt < 2; mt++) {
                    const __half* ap = S + (((wr * 2 + mt) * 2 + ki) * 32 + lane) * 8;
                    ah[mt] = *reinterpret_cast<const uint4*>(ap);
                    al[mt] = *reinterpret_cast<const uint4*>(ap + 4096);
                }
                uint2 bh[4], bl[4];
#pragma unroll
                for (int nt = 0; nt < 4; nt++) {
                    const __half* bp = SB + ((wc * 4 + nt) * 32 + lane) * 8 + ki * 4;
                    bh[nt] = *reinterpret_cast<const uint2*>(bp);
                    bl[nt] = *reinterpret_cast<const uint2*>(bp + 4096);
                }
#pragma unroll
                for (int mt = 0; mt < 2; mt++)
#pragma unroll
                    for (int nt = 0; nt < 4; nt++)
                        mma16(acc[mt][nt], ah[mt], bh[nt].x, bh[nt].y);
#pragma unroll
                for (int mt = 0; mt < 2; mt++)
#pragma unroll
                    for (int nt = 0; nt < 4; nt++)
                        mma16(acc[mt][nt], ah[mt], bl[nt].x, bl[nt].y);
#pragma unroll
                for (int mt = 0; mt < 2; mt++)
#pragma unroll
                    for (int nt = 0; nt < 4; nt++)
                        mma16(acc[mt][nt], al[mt], bh[nt].x, bh[nt].y);
            }
        }

        if (lane == 0) mbar_arrive(mb + 24 + slot * 8);   // consumed
        if (lane == 0 && pr + 3 < NPAIR && wid == ((pr + 3) & 15))
            issue(pr + 3);
    }

    // ---------------- epilogue ----------------
    if (store) {
        float mR0[2], mR1[2], mS0[2], mS1[2];
#pragma unroll
        for (int mt = 0; mt < 2; mt++) {
            mR0[mt] = mR1[mt] = mS0[mt] = mS1[mt] = -3.402823466e38f;
        }
#pragma unroll
        for (int mt = 0; mt < 2; mt++) {
            int r = rowBase + wr * 32 + mt * 16 + g;
#pragma unroll
            for (int nt = 0; nt < 4; nt++) {
                int c = colBase + wc * 32 + nt * 8 + 2 * t;
                float ib0 = g_invb[c], ib1 = g_invb[c + 1];
                float a0 = acc[mt][nt][0], a1 = acc[mt][nt][1];
                float a2 = acc[mt][nt][2], a3 = acc[mt][nt][3];
                mR0[mt] = fmaxf(mR0[mt], fmaxf(a0, a1));
                mR1[mt] = fmaxf(mR1[mt], fmaxf(a2, a3));
                mS0[mt] = fmaxf(mS0[mt], fmaxf(a0 * ib0, a1 * ib1));
                mS1[mt] = fmaxf(mS1[mt], fmaxf(a2 * ib0, a3 * ib1));
                *reinterpret_cast<float2*>(Rout + (size_t)r * NMOD + c) =
                    make_float2(a0, a1);
                *reinterpret_cast<float2*>(Rout + (size_t)(r + 8) * NMOD + c) =
                    make_float2(a2, a3);
            }
        }
#pragma unroll
        for (int mt = 0; mt < 2; mt++) {
#pragma unroll
            for (int o = 1; o <= 2; o <<= 1) {
                mR0[mt] = fmaxf(mR0[mt], __shfl_xor_sync(0xFFFFFFFF, mR0[mt], o));
                mR1[mt] = fmaxf(mR1[mt], __shfl_xor_sync(0xFFFFFFFF, mR1[mt], o));
                mS0[mt] = fmaxf(mS0[mt], __shfl_xor_sync(0xFFFFFFFF, mS0[mt], o));
                mS1[mt] = fmaxf(mS1[mt], __shfl_xor_sync(0xFFFFFFFF, mS1[mt], o));
            }
        }
        if (t == 0) {
#pragma unroll
            for (int mt = 0; mt < 2; mt++) {
                int r = rowBase + wr * 32 + mt * 16 + g;
                atomicMax(&g_posmaxR[r], fenc(mR0[mt]));
                atomicMax(&g_posmaxR[r + 8], fenc(mR1[mt]));
                atomicMax(&g_posmaxS[r], fenc(mS0[mt]));
                atomicMax(&g_posmaxS[r + 8], fenc(mS1[mt]));
            }
        }
    } else {
        float mx0[2], mx1[2];
#pragma unroll
        for (int mt = 0; mt < 2; mt++) { mx0[mt] = -3.402823466e38f; mx1[mt] = -3.402823466e38f; }
#pragma unroll
        for (int nt = 0; nt < 4; nt++) {
            int c = colBase + wc * 32 + nt * 8 + 2 * t;
            float ic0 = g_invc[c], ic1 = g_invc[c + 1];
#pragma unroll
            for (int mt = 0; mt < 2; mt++) {
                mx0[mt] = fmaxf(mx0[mt], fmaxf(acc[mt][nt][0] * ic0, acc[mt][nt][1] * ic1));
                mx1[mt] = fmaxf(mx1[mt], fmaxf(acc[mt][nt][2] * ic0, acc[mt][nt][3] * ic1));
            }
        }
#pragma unroll
        for (int mt = 0; mt < 2; mt++) {
            mx0[mt] = fmaxf(mx0[mt], __shfl_xor_sync(0xFFFFFFFF, mx0[mt], 1));
            mx0[mt] = fmaxf(mx0[mt], __shfl_xor_sync(0xFFFFFFFF, mx0[mt], 2));
            mx1[mt] = fmaxf(mx1[mt], __shfl_xor_sync(0xFFFFFFFF, mx1[mt], 1));
            mx1[mt] = fmaxf(mx1[mt], __shfl_xor_sync(0xFFFFFFFF, mx1[mt], 2));
        }
        if (t == 0) {
#pragma unroll
            for (int mt = 0; mt < 2; mt++) {
                int r = rowBase + wr * 32 + mt * 16 + g;
                atomicMax(&g_negmax[r], fenc(mx0[mt]));
                atomicMax(&g_negmax[r + 8], fenc(mx1[mt]));
            }
        }
    }
}

// ---------------- single-pass row softmax ----------------
__global__ __launch_bounds__(512)
void row_stats_kernel(float* __restrict__ attn, float* __restrict__ perstep_out) {
    __shared__ float sm[32];
    __shared__ float bc[2];
    const int row = blockIdx.x;
    const int tid = threadIdx.x;
    const int lane = tid & 31, wid = tid >> 5;
    float* Rrow = attn + (size_t)row * NMOD;
    const float maxR = fdec(g_posmaxR[row]);

    float e[8];
    float dsum = 0.0f, ws = 0.0f;
#pragma unroll
    for (int q = 0; q < 8; q++) {
        int j = tid + q * 512;
        float v  = Rrow[j];
        float ev = __expf((v - maxR) * INVT);
        e[q] = ev;
        dsum += ev;
        ws   += v * g_invb[j] * ev;
    }
#pragma unroll
    for (int o = 16; o > 0; o >>= 1) {
        dsum += __shfl_xor_sync(0xFFFFFFFF, dsum, o);
        ws   += __shfl_xor_sync(0xFFFFFFFF, ws,   o);
    }
    if (lane == 0) { sm[wid] = dsum; sm[16 + wid] = ws; }
    __syncthreads();
    if (tid == 0) {
        float a = sm[0], b = sm[16];
#pragma unroll
        for (int w = 1; w < 16; w++) {
            a += sm[w];
            b += sm[16 + w];
        }
        bc[0] = a; bc[1] = b;
    }
    __syncthreads();

    const float invd = 1.0f / bc[0];
#pragma unroll
    for (int q = 0; q < 8; q++)
        Rrow[tid + q * 512] = e[q] * invd;

    if (tid == 0) {
        float inva = g_inva[row];
        float ps = fdec(g_posmaxS[row]) * inva;
        g_perstep[row]  = ps;
        perstep_out[row] = ps;
        g_wsum[row] = inva * bc[1] * invd;
    }
}

// ---------------- final scalar reductions ----------------
__global__ void finalize_kernel(float* __restrict__ out) {
    __shared__ float r0[1024], r1[1024], r2[1024], r3[1024];
    const int tid = threadIdx.x;
    float s = 0.0f, mn = 3.402823466e38f, ws = 0.0f, ng = 0.0f;
#pragma unroll
    for (int q = 0; q < 8; q++) {
        int i = tid + q * 1024;
        float ps = g_perstep[i];
        s += ps;
        mn = fminf(mn, ps);
        ws += g_wsum[i];
        ng += fdec(g_negmax[i]) * g_inva[i];
    }
    r0[tid] = s; r1[tid] = mn; r2[tid] = ws; r3[tid] = ng;
    __syncthreads();
    for (int off = 512; off > 0; off >>= 1) {
        if (tid < off) {
            r0[tid] += r0[tid + off];
            r1[tid] = fminf(r1[tid], r1[tid + off]);
            r2[tid] += r2[tid + off];
            r3[tid] += r3[tid + off];
        }
        __syncthreads();
    }
    if (tid == 0) {
        float alignment = r0[0] * (1.0f / NSTEP);
        float weighted  = r2[0] * (1.0f / NSTEP);
        float neg       = r3[0] * (1.0f / NSTEP);
        float contrast  = alignment - neg;
        float margin    = fmaxf(contrast - 0.2f, 0.0f);
        float overall   = 0.7f * weighted + 0.3f * contrast;
        out[0] = alignment;
        out[1] = weighted;
        float* tl = out + 2 + (size_t)NSTEP * NMOD;
        tl[0] = contrast;
        tl[1] = margin;
        tl[2] = alignment;
        tl[3] = neg;
        tl[4 + NSTEP] = r1[0];
        tl[5 + NSTEP] = overall;
    }
}

// ---------------- launch ----------------
extern "C" void kernel_launch(void* const* d_in, const int* in_sizes, int n_in,
                              void* d_out, int out_size) {
    (void)in_sizes; (void)n_in; (void)out_size;
    const float* A = (const float*)d_in[0];
    const float* B = (const float*)d_in[1];
    const float* C = (const float*)d_in[2];
    float* out  = (float*)d_out;
    float* attn = out + 2;
    float* perstep = out + 2 + (size_t)NSTEP * NMOD + 4;

    __half* As_p; cudaGetSymbolAddress((void**)&As_p, g_As);
    __half* Bs_p; cudaGetSymbolAddress((void**)&Bs_p, g_Bs);
    __half* Cs_p; cudaGetSymbolAddress((void**)&Cs_p, g_Cs);

    cudaFuncSetAttribute(gemm_mma, cudaFuncAttributeMaxDynamicSharedMemorySize, SMEM_BYTES);

    prep_kernel<<<6144, 256>>>(A, B, C);
    gemm_mma<<<dim3(64, 64), 512, SMEM_BYTES>>>(As_p, Bs_p, Cs_p, attn);
    row_stats_kernel<<<NSTEP, 512>>>(attn, perstep);
    finalize_kernel<<<1, 1024>>>(out);
}